// round 1
// baseline (speedup 1.0000x reference)
#include <cuda_runtime.h>

#define THREADS 256
#define NQ 12
#define DIM 4096
#define NL 4

// XOR swizzle on float2-indexed shared state: makes every access pattern in
// this kernel conflict-free per half-warp (16 lanes x 8B = one 128B phase).
__device__ __forceinline__ int swz(int i) { return i ^ ((i >> 4) & 15); }

// Ring-CNOT permutation: new_state[i] = old_state[perm_fwd(i)].
// Reference composes gates (c=j, t=(j+1)%12), j=0..11; composed map applies
// gate j=11 FIRST when evaluating perm(i). qubit q <-> bit (11-q).
__device__ __forceinline__ int perm_fwd(int i) {
#pragma unroll
    for (int j = 11; j >= 0; j--) {
        int cb = 11 - j;                      // control bit
        int tb = (j == 11) ? 11 : (10 - j);   // target bit
        i ^= ((i >> cb) & 1) << tb;
    }
    return i;
}

// Inverse permutation (CNOTs are involutions; reverse application order).
__device__ __forceinline__ int perm_inv(int i) {
#pragma unroll
    for (int j = 0; j < 12; j++) {
        int cb = 11 - j;
        int tb = (j == 11) ? 11 : (10 - j);
        i ^= ((i >> cb) & 1) << tb;
    }
    return i;
}

__global__ void __launch_bounds__(THREADS, 3) qsim_kernel(
    const float* __restrict__ x, const float* __restrict__ w,
    float* __restrict__ out)
{
    __shared__ float2 st[DIM];        // 32 KB state, swizzled layout
    __shared__ float gc[60], gs[60];  // cos/sin of half-angles, gate order
    __shared__ float red[NQ];

    const int b = blockIdx.x;
    const int t = threadIdx.x;

    // Gate angle table: gates 0..11 = RX(x[b,j]); 12+l*12+j = RX(weights[l,j]).
    if (t < 60) {
        float th = (t < NQ) ? x[b * NQ + t] : w[t - NQ];
        float ss, cc;
        sincosf(0.5f * th, &ss, &cc);
        gc[t] = cc; gs[t] = ss;
    }
    if (t < NQ) red[t] = 0.0f;

    float2 a[16];  // 16 amplitudes spanning 4 qubit bits

    // logical index for local amp l in a pass covering bit field [shift+3:shift]
    auto lidx = [&](int shift, int l) -> int {
        if (shift == 8) return (l << 8) | t;
        if (shift == 4) return ((t >> 4) << 8) | (l << 4) | (t & 15);
        return (t << 4) | l;
    };

    auto load = [&](int shift) {
#pragma unroll
        for (int l = 0; l < 16; l++) a[l] = st[swz(lidx(shift, l))];
    };
    auto store = [&](int shift) {
#pragma unroll
        for (int l = 0; l < 16; l++) st[swz(lidx(shift, l))] = a[l];
    };
    // Group-A load with the previous layer's CNOT permutation folded in.
    // perm is GF(2)-linear and (l<<8), t occupy disjoint bits:
    // perm((l<<8)|t) = perm(l<<8) ^ perm(t); perm(l<<8) constant-folds.
    auto loadA_perm = [&]() {
        int pt = perm_fwd(t);
#pragma unroll
        for (int l = 0; l < 16; l++)
            a[l] = st[swz(perm_fwd(l << 8) ^ pt)];
    };

    // RX(theta) on the in-register bit with mask m (1<<(3-q_in_group)):
    // n0 = c*s0 - i*s*s1 ; n1 = -i*s*s0 + c*s1
    auto rx = [&](int g, int m) {
        float c = gc[g], s = gs[g];
#pragma unroll
        for (int l = 0; l < 16; l++) {
            if (!(l & m)) {
                int l1 = l | m;
                float2 a0 = a[l], a1 = a[l1];
                a[l].x  = c * a0.x + s * a1.y;
                a[l].y  = c * a0.y - s * a1.x;
                a[l1].x = c * a1.x + s * a0.y;
                a[l1].y = c * a1.y - s * a0.x;
            }
        }
    };

    __syncthreads();

    // ---- Initial data-encoding layer: RX(x[b,j]) on all 12 qubits ----
    // Pass 1 (qubits 0-3, bits 11-8): initial state |0..0> needs no load.
#pragma unroll
    for (int l = 0; l < 16; l++) a[l] = make_float2(0.0f, 0.0f);
    if (t == 0) a[0].x = 1.0f;
    rx(0, 8); rx(1, 4); rx(2, 2); rx(3, 1);
    store(8); __syncthreads();

    load(4); rx(4, 8); rx(5, 4); rx(6, 2); rx(7, 1); store(4); __syncthreads();
    load(0); rx(8, 8); rx(9, 4); rx(10, 2); rx(11, 1); store(0); __syncthreads();

    // ---- 4 weight layers: 12 RX + ring-CNOT perm each ----
#pragma unroll 1
    for (int layer = 0; layer < NL; layer++) {
        int g = 12 + layer * 12;
        // Group A (qubits 0-3). For layer>0, fold in the previous layer's perm.
        if (layer == 0) {
            load(8);
            rx(g, 8); rx(g + 1, 4); rx(g + 2, 2); rx(g + 3, 1);
        } else {
            loadA_perm();
            rx(g, 8); rx(g + 1, 4); rx(g + 2, 2); rx(g + 3, 1);
            __syncthreads();  // scattered reads must complete before any store
        }
        store(8); __syncthreads();

        load(4); rx(g + 4, 8); rx(g + 5, 4); rx(g + 6, 2); rx(g + 7, 1);
        store(4); __syncthreads();

        load(0); rx(g + 8, 8); rx(g + 9, 4); rx(g + 10, 2); rx(g + 11, 1);
        if (layer < NL - 1) { store(0); __syncthreads(); }
        // Last layer: amps stay in registers; the final perm is handled in the
        // readout below via perm_inv (signs only depend on the final index).
    }

    // ---- Readout: <Z_q> = sum_i |amp_i|^2 * (1 - 2*bit_{11-q}(i)) ----
    float acc[NQ];
#pragma unroll
    for (int q = 0; q < NQ; q++) acc[q] = 0.0f;
    int pit = perm_inv(t << 4);  // linear: perm_inv((t<<4)|l) = perm_inv(t<<4)^perm_inv(l)
#pragma unroll
    for (int l = 0; l < 16; l++) {
        int fin = pit ^ perm_inv(l);  // index after the (unmaterialized) last perm
        float p = a[l].x * a[l].x + a[l].y * a[l].y;
#pragma unroll
        for (int q = 0; q < NQ; q++)
            acc[q] += (fin & (1 << (11 - q))) ? -p : p;
    }
    // Warp reduce then one atomic per warp per observable.
#pragma unroll
    for (int off = 16; off > 0; off >>= 1) {
#pragma unroll
        for (int q = 0; q < NQ; q++)
            acc[q] += __shfl_xor_sync(0xffffffffu, acc[q], off);
    }
    if ((t & 31) == 0) {
#pragma unroll
        for (int q = 0; q < NQ; q++) atomicAdd(&red[q], acc[q]);
    }
    __syncthreads();
    if (t < NQ) out[b * NQ + t] = red[t];
}

extern "C" void kernel_launch(void* const* d_in, const int* in_sizes, int n_in,
                              void* d_out, int out_size) {
    const float* x = (const float*)d_in[0];   // (64,128,12) float32
    const float* w = (const float*)d_in[1];   // (4,12) float32
    float* out = (float*)d_out;               // (64,128,12) float32
    int B = in_sizes[0] / NQ;                 // 8192
    qsim_kernel<<<B, THREADS>>>(x, w, out);
}

// round 3
// speedup vs baseline: 1.1103x; 1.1103x over previous
#include <cuda_runtime.h>

#define THREADS 256
#define NQ 12
#define DIM 4096
#define NL 4

using u64 = unsigned long long;

// ---- packed f32x2 helpers (Blackwell dual-FMA path) ----
__device__ __forceinline__ u64 pk2(float lo, float hi) {
    u64 r; asm("mov.b64 %0,{%1,%2};" : "=l"(r) : "f"(lo), "f"(hi)); return r;
}
__device__ __forceinline__ void upk2(u64 v, float& lo, float& hi) {
    asm("mov.b64 {%0,%1},%2;" : "=f"(lo), "=f"(hi) : "l"(v));
}
__device__ __forceinline__ u64 fma2(u64 a, u64 b, u64 c) {
    u64 d; asm("fma.rn.f32x2 %0,%1,%2,%3;" : "=l"(d) : "l"(a), "l"(b), "l"(c)); return d;
}
__device__ __forceinline__ u64 mul2(u64 a, u64 b) {
    u64 d; asm("mul.rn.f32x2 %0,%1,%2;" : "=l"(d) : "l"(a), "l"(b)); return d;
}

// XOR swizzle on float2-indexed shared state: conflict-free for all three
// group access patterns (verified per half-warp bank analysis).
__device__ __forceinline__ int swz(int i) { return i ^ ((i >> 4) & 15); }

// Ring-CNOT permutation: new_state[i] = old_state[perm_fwd(i)].
__device__ __forceinline__ int perm_fwd(int i) {
#pragma unroll
    for (int j = 11; j >= 0; j--) {
        int cb = 11 - j;
        int tb = (j == 11) ? 11 : (10 - j);
        i ^= ((i >> cb) & 1) << tb;
    }
    return i;
}
__device__ __forceinline__ int perm_inv(int i) {
#pragma unroll
    for (int j = 0; j < 12; j++) {
        int cb = 11 - j;
        int tb = (j == 11) ? 11 : (10 - j);
        i ^= ((i >> cb) & 1) << tb;
    }
    return i;
}

__global__ void __launch_bounds__(THREADS, 3) qsim_kernel(
    const float* __restrict__ x, const float* __restrict__ w,
    float* __restrict__ out)
{
    __shared__ float2 st[DIM];        // 32 KB state, swizzled
    __shared__ float gc[60], gs[60];
    __shared__ float red[NQ];

    const int b = blockIdx.x;
    const int t = threadIdx.x;

    if (t < 60) {
        float th = (t < NQ) ? x[b * NQ + t] : w[t - NQ];
        float ss, cc;
        sincosf(0.5f * th, &ss, &cc);
        gc[t] = cc; gs[t] = ss;
    }
    if (t < NQ) red[t] = 0.0f;

    // Packed state: 16 amps as 8 SoA packs. Pack k = amps (l=2k, l=2k+1).
    u64 X[8], Y[8];

    // logical index for local amp l; group covers index bits [shift+3:shift]
    auto lidx = [&](int shift, int l) -> int {
        if (shift == 8) return (l << 8) | t;
        if (shift == 4) return ((t >> 4) << 8) | (l << 4) | (t & 15);
        return (t << 4) | l;
    };

    // Apply the pack-bit gate (l-mask 1) scalar on a freshly loaded pair, pack.
    auto gate_pack = [&](float2 a0, float2 a1, float c1, float s1, int k) {
        float nx0 = fmaf(c1, a0.x,  s1 * a1.y);
        float ny0 = fmaf(c1, a0.y, -s1 * a1.x);
        float nx1 = fmaf(c1, a1.x,  s1 * a0.y);
        float ny1 = fmaf(c1, a1.y, -s1 * a0.x);
        X[k] = pk2(nx0, nx1);
        Y[k] = pk2(ny0, ny1);
    };

    // Packed RX on pack-space bit pm (l-space mask = pm<<1). Fully f32x2.
    auto rxp = [&](int g, int pm) {
        float c = gc[g], s = gs[g];
        u64 c2 = pk2(c, c), s2 = pk2(s, s), n2 = pk2(-s, -s);
#pragma unroll
        for (int k = 0; k < 8; k++) {
            if (!(k & pm)) {
                int k1 = k | pm;
                u64 X0 = X[k], Y0 = Y[k], X1 = X[k1], Y1 = Y[k1];
                X[k]  = fma2(c2, X0, mul2(s2, Y1));
                Y[k]  = fma2(c2, Y0, mul2(n2, X1));
                X[k1] = fma2(c2, X1, mul2(s2, Y0));
                Y[k1] = fma2(c2, Y1, mul2(n2, X0));
            }
        }
    };
    // Gates g..g+3 act on l-masks 8,4,2,1. g+3 was applied at load; do the rest.
    auto packed3 = [&](int g) { rxp(g, 4); rxp(g + 1, 2); rxp(g + 2, 1); };

    auto load_pass = [&](int g, int shift) {
        float c1 = gc[g + 3], s1 = gs[g + 3];
#pragma unroll
        for (int k = 0; k < 8; k++)
            gate_pack(st[swz(lidx(shift, 2 * k))], st[swz(lidx(shift, 2 * k + 1))],
                      c1, s1, k);
    };
    // Group-A load with the previous layer's CNOT perm folded in (GF(2)-linear).
    auto load_pass_perm = [&](int g) {
        float c1 = gc[g + 3], s1 = gs[g + 3];
        int pt = perm_fwd(t);
#pragma unroll
        for (int k = 0; k < 8; k++)
            gate_pack(st[swz(perm_fwd((2 * k) << 8) ^ pt)],
                      st[swz(perm_fwd((2 * k + 1) << 8) ^ pt)], c1, s1, k);
    };
    auto store_pass = [&](int shift) {
#pragma unroll
        for (int k = 0; k < 8; k++) {
            float x0, x1, y0, y1;
            upk2(X[k], x0, x1);
            upk2(Y[k], y0, y1);
            st[swz(lidx(shift, 2 * k))]     = make_float2(x0, y0);
            st[swz(lidx(shift, 2 * k + 1))] = make_float2(x1, y1);
        }
    };

    __syncthreads();

    // ---- Initial data-encoding layer (x angles), group A on |0..0> ----
    {
        float c1 = gc[3], s1 = gs[3];
#pragma unroll
        for (int k = 0; k < 8; k++) {
            float2 a0 = make_float2(0.0f, 0.0f), a1 = a0;
            if (t == 0 && k == 0) a0.x = 1.0f;
            gate_pack(a0, a1, c1, s1, k);
        }
        packed3(0);
        store_pass(8); __syncthreads();
    }
    load_pass(4, 4); packed3(4); store_pass(4); __syncthreads();
    load_pass(8, 0); packed3(8); store_pass(0); __syncthreads();

    // ---- 4 weight layers: 12 RX + ring-CNOT perm each ----
#pragma unroll 1
    for (int layer = 0; layer < NL; layer++) {
        int g = 12 + layer * 12;
        if (layer == 0) {
            load_pass(g, 8);
            packed3(g);
        } else {
            load_pass_perm(g);   // scattered reads
            packed3(g);
            __syncthreads();     // reads done before anyone stores
        }
        store_pass(8); __syncthreads();

        load_pass(g + 4, 4); packed3(g + 4); store_pass(4); __syncthreads();

        load_pass(g + 8, 0); packed3(g + 8);
        if (layer < NL - 1) { store_pass(0); __syncthreads(); }
        // last layer: stays in registers; final perm folded into readout below
    }

    // ---- Readout: <Z_q> = sum_i p_i * (1 - 2*bit_{11-q}(i_final)) ----
    float acc[NQ];
#pragma unroll
    for (int q = 0; q < NQ; q++) acc[q] = 0.0f;
    int pit = perm_inv(t << 4);
#pragma unroll
    for (int k = 0; k < 8; k++) {
        u64 P = fma2(X[k], X[k], mul2(Y[k], Y[k]));  // packed |amp|^2 pair
        float p0, p1;
        upk2(P, p0, p1);
        int f0 = pit ^ perm_inv(2 * k);
        int f1 = pit ^ perm_inv(2 * k + 1);
#pragma unroll
        for (int q = 0; q < NQ; q++) {
            acc[q] += (f0 & (1 << (11 - q))) ? -p0 : p0;
            acc[q] += (f1 & (1 << (11 - q))) ? -p1 : p1;
        }
    }
#pragma unroll
    for (int off = 16; off > 0; off >>= 1) {
#pragma unroll
        for (int q = 0; q < NQ; q++)
            acc[q] += __shfl_xor_sync(0xffffffffu, acc[q], off);
    }
    if ((t & 31) == 0) {
#pragma unroll
        for (int q = 0; q < NQ; q++) atomicAdd(&red[q], acc[q]);
    }
    __syncthreads();
    if (t < NQ) out[b * NQ + t] = red[t];
}

extern "C" void kernel_launch(void* const* d_in, const int* in_sizes, int n_in,
                              void* d_out, int out_size) {
    const float* x = (const float*)d_in[0];   // (64,128,12) float32
    const float* w = (const float*)d_in[1];   // (4,12) float32
    float* out = (float*)d_out;               // (64,128,12) float32
    int B = in_sizes[0] / NQ;                 // 8192
    qsim_kernel<<<B, THREADS>>>(x, w, out);
}

// round 4
// speedup vs baseline: 1.7946x; 1.6163x over previous
#include <cuda_runtime.h>

#define THREADS 256
#define NQ 12
#define DIM 4096

using u64 = unsigned long long;

// ---- packed f32x2 helpers ----
__device__ __forceinline__ u64 pk2(float lo, float hi) {
    u64 r; asm("mov.b64 %0,{%1,%2};" : "=l"(r) : "f"(lo), "f"(hi)); return r;
}
__device__ __forceinline__ void upk2(u64 v, float& lo, float& hi) {
    asm("mov.b64 {%0,%1},%2;" : "=f"(lo), "=f"(hi) : "l"(v));
}
__device__ __forceinline__ u64 fma2(u64 a, u64 b, u64 c) {
    u64 d; asm("fma.rn.f32x2 %0,%1,%2,%3;" : "=l"(d) : "l"(a), "l"(b), "l"(c)); return d;
}
__device__ __forceinline__ u64 mul2(u64 a, u64 b) {
    u64 d; asm("mul.rn.f32x2 %0,%1,%2;" : "=l"(d) : "l"(a), "l"(b)); return d;
}

// XOR swizzle on float2-indexed shared state (conflict-free for all patterns)
__device__ __forceinline__ int swz(int i) { return i ^ ((i >> 4) & 15); }

// Ring-CNOT permutation: new_state[i] = old_state[perm_fwd(i)]
__device__ __forceinline__ int perm_fwd(int i) {
#pragma unroll
    for (int j = 11; j >= 0; j--) {
        int cb = 11 - j;
        int tb = (j == 11) ? 11 : (10 - j);
        i ^= ((i >> cb) & 1) << tb;
    }
    return i;
}
__device__ __forceinline__ int perm_inv(int i) {
#pragma unroll
    for (int j = 0; j < 12; j++) {
        int cb = 11 - j;
        int tb = (j == 11) ? 11 : (10 - j);
        i ^= ((i >> cb) & 1) << tb;
    }
    return i;
}

__global__ void __launch_bounds__(THREADS, 3) qsim_kernel(
    const float* __restrict__ x, const float* __restrict__ w,
    float* __restrict__ out)
{
    __shared__ float2 st[DIM];          // 32 KB state, swizzled
    __shared__ float gc[48], gs[48];    // merged layer0 in slots 0-11; layers 1-3 in 12-47
    __shared__ float sLA[16], sLB[16], sLC[16];  // product-state magnitude LUTs
    __shared__ float red[NQ];

    const int b = blockIdx.x;
    const int t = threadIdx.x;

    // Angle table. Slots 0-11: theta = x_q + w_{0,q} (RX fusion: encoding layer
    // merged with weight layer 0). Slots 12-47: w rows 1..3 (same linear index).
    if (t < 48) {
        float th = w[t];
        if (t < NQ) th += x[b * NQ + t];
        float ss, cc;
        sincosf(0.5f * th, &ss, &cc);
        gc[t] = cc; gs[t] = ss;
    }
    if (t < NQ) red[t] = 0.0f;
    __syncthreads();

    // Product-state magnitude LUTs over the three 4-bit nibbles.
    // Qubit q <-> index bit (11-q). Nibble A = bits 11:8 (qubits 0-3), etc.
    if (t < 48) {
        int grp = t >> 4;                // 0:A, 1:B, 2:C
        int h = t & 15;
        int qbase = grp * 4;
        float p = 1.0f;
#pragma unroll
        for (int q = 0; q < 4; q++)
            p *= ((h >> (3 - q)) & 1) ? gs[qbase + q] : gc[qbase + q];
        (grp == 0 ? sLA : grp == 1 ? sLB : sLC)[h] = p;
    }

    u64 X[8], Y[8];  // SoA packed state: pack k holds amps l=2k, 2k+1

    auto lidx = [&](int shift, int l) -> int {
        if (shift == 8) return (l << 8) | t;
        if (shift == 4) return ((t >> 4) << 8) | (l << 4) | (t & 15);
        return (t << 4) | l;
    };

    // pack-bit gate (l-mask 1) scalar on a pair, then SoA-pack
    auto gate_pack = [&](float2 a0, float2 a1, float c1, float s1, int k) {
        float nx0 = fmaf(c1, a0.x,  s1 * a1.y);
        float ny0 = fmaf(c1, a0.y, -s1 * a1.x);
        float nx1 = fmaf(c1, a1.x,  s1 * a0.y);
        float ny1 = fmaf(c1, a1.y, -s1 * a0.x);
        X[k] = pk2(nx0, nx1);
        Y[k] = pk2(ny0, ny1);
    };

    auto rxp = [&](int g, int pm) {
        float c = gc[g], s = gs[g];
        u64 c2 = pk2(c, c), s2 = pk2(s, s), n2 = pk2(-s, -s);
#pragma unroll
        for (int k = 0; k < 8; k++) {
            if (!(k & pm)) {
                int k1 = k | pm;
                u64 X0 = X[k], Y0 = Y[k], X1 = X[k1], Y1 = Y[k1];
                X[k]  = fma2(c2, X0, mul2(s2, Y1));
                Y[k]  = fma2(c2, Y0, mul2(n2, X1));
                X[k1] = fma2(c2, X1, mul2(s2, Y0));
                Y[k1] = fma2(c2, Y1, mul2(n2, X0));
            }
        }
    };
    auto packed3 = [&](int g) { rxp(g, 4); rxp(g + 1, 2); rxp(g + 2, 1); };

    auto load_pass = [&](int g, int shift) {
        float c1 = gc[g + 3], s1 = gs[g + 3];
#pragma unroll
        for (int k = 0; k < 8; k++)
            gate_pack(st[swz(lidx(shift, 2 * k))], st[swz(lidx(shift, 2 * k + 1))],
                      c1, s1, k);
    };
    auto load_pass_perm = [&](int g) {
        float c1 = gc[g + 3], s1 = gs[g + 3];
        int pt = perm_fwd(t);
#pragma unroll
        for (int k = 0; k < 8; k++)
            gate_pack(st[swz(perm_fwd((2 * k) << 8) ^ pt)],
                      st[swz(perm_fwd((2 * k + 1) << 8) ^ pt)], c1, s1, k);
    };
    auto store_pass = [&](int shift) {
#pragma unroll
        for (int k = 0; k < 8; k++) {
            float x0, x1, y0, y1;
            upk2(X[k], x0, x1);
            upk2(Y[k], y0, y1);
            st[swz(lidx(shift, 2 * k))]     = make_float2(x0, y0);
            st[swz(lidx(shift, 2 * k + 1))] = make_float2(x1, y1);
        }
    };

    // Analytic product-state amplitude at arbitrary index pi:
    // amp = mag(pi) * (-i)^popc(pi)
    auto prod_amp = [&](int pi) -> float2 {
        float mag = sLA[pi >> 8] * sLB[(pi >> 4) & 15] * sLC[pi & 15];
        int kc = __popc(pi) & 3;
        float sm = __int_as_float(__float_as_int(mag) ^ (((kc + 1) & 2) << 30));
        return (kc & 1) ? make_float2(0.0f, sm) : make_float2(sm, 0.0f);
    };

    __syncthreads();  // LUTs ready

    // ---- Layer 1 (gates 12-23): group A computed analytically at the
    // perm-permuted indices of the (merged encode+layer0) product state. ----
    {
        int pt = perm_fwd(t);
        float c1 = gc[15], s1 = gs[15];
#pragma unroll
        for (int k = 0; k < 8; k++)
            gate_pack(prod_amp(perm_fwd((2 * k) << 8) ^ pt),
                      prod_amp(perm_fwd((2 * k + 1) << 8) ^ pt), c1, s1, k);
        packed3(12);
        store_pass(8); __syncthreads();

        load_pass(16, 4); packed3(16); store_pass(4); __syncthreads();
        load_pass(20, 0); packed3(20); store_pass(0); __syncthreads();
    }

    // ---- Layers 2,3 (gates 24-35, 36-47) ----
#pragma unroll 1
    for (int layer = 2; layer <= 3; layer++) {
        int g = layer * 12;
        load_pass_perm(g);   // scattered reads fold in the previous perm
        packed3(g);
        __syncthreads();     // reads complete before overwrite
        store_pass(8); __syncthreads();

        load_pass(g + 4, 4); packed3(g + 4); store_pass(4); __syncthreads();

        load_pass(g + 8, 0); packed3(g + 8);
        if (layer < 3) { store_pass(0); __syncthreads(); }
        // layer 3: stays in registers; final perm folded into readout
    }

    // ---- Readout: <Z_q> = sum_i p_i * (1-2*bit_{11-q}(perm(i))) ----
    // sign(l,q) compile-time (FADD neg modifier); sign_t(q) via 1 XOR at end.
    float acc[NQ];
#pragma unroll
    for (int q = 0; q < NQ; q++) acc[q] = 0.0f;
#pragma unroll
    for (int k = 0; k < 8; k++) {
        u64 P = fma2(X[k], X[k], mul2(Y[k], Y[k]));
        float p0, p1;
        upk2(P, p0, p1);
        const int pil0 = perm_inv(2 * k);      // compile-time constants
        const int pil1 = perm_inv(2 * k + 1);
#pragma unroll
        for (int q = 0; q < NQ; q++) {
            acc[q] += ((pil0 >> (11 - q)) & 1) ? -p0 : p0;
            acc[q] += ((pil1 >> (11 - q)) & 1) ? -p1 : p1;
        }
    }
    {
        int pit = perm_inv(t << 4);  // runtime sign factor per thread
#pragma unroll
        for (int q = 0; q < NQ; q++)
            acc[q] = __int_as_float(__float_as_int(acc[q]) ^
                                    (((pit >> (11 - q)) & 1) << 31));
    }
#pragma unroll
    for (int off = 16; off > 0; off >>= 1) {
#pragma unroll
        for (int q = 0; q < NQ; q++)
            acc[q] += __shfl_xor_sync(0xffffffffu, acc[q], off);
    }
    if ((t & 31) == 0) {
#pragma unroll
        for (int q = 0; q < NQ; q++) atomicAdd(&red[q], acc[q]);
    }
    __syncthreads();
    if (t < NQ) out[b * NQ + t] = red[t];
}

extern "C" void kernel_launch(void* const* d_in, const int* in_sizes, int n_in,
                              void* d_out, int out_size) {
    const float* x = (const float*)d_in[0];   // (64,128,12) float32
    const float* w = (const float*)d_in[1];   // (4,12) float32
    float* out = (float*)d_out;               // (64,128,12) float32
    int B = in_sizes[0] / NQ;                 // 8192
    qsim_kernel<<<B, THREADS>>>(x, w, out);
}

// round 5
// speedup vs baseline: 2.0816x; 1.1599x over previous
#include <cuda_runtime.h>

#define THREADS 256
#define NQ 12
#define DIM 4096

using u64 = unsigned long long;

// ---- packed f32x2 helpers ----
__device__ __forceinline__ u64 pk2(float lo, float hi) {
    u64 r; asm("mov.b64 %0,{%1,%2};" : "=l"(r) : "f"(lo), "f"(hi)); return r;
}
__device__ __forceinline__ void upk2(u64 v, float& lo, float& hi) {
    asm("mov.b64 {%0,%1},%2;" : "=f"(lo), "=f"(hi) : "l"(v));
}
__device__ __forceinline__ u64 fma2(u64 a, u64 b, u64 c) {
    u64 d; asm("fma.rn.f32x2 %0,%1,%2,%3;" : "=l"(d) : "l"(a), "l"(b), "l"(c)); return d;
}
__device__ __forceinline__ u64 mul2(u64 a, u64 b) {
    u64 d; asm("mul.rn.f32x2 %0,%1,%2;" : "=l"(d) : "l"(a), "l"(b)); return d;
}

// XOR swizzle on float2-indexed shared state (conflict-free for all patterns)
__device__ __forceinline__ int swz(int i) { return i ^ ((i >> 4) & 15); }

// Ring-CNOT permutation: new_state[i] = old_state[perm_fwd(i)]
__device__ __forceinline__ int perm_fwd(int i) {
#pragma unroll
    for (int j = 11; j >= 0; j--) {
        int cb = 11 - j;
        int tb = (j == 11) ? 11 : (10 - j);
        i ^= ((i >> cb) & 1) << tb;
    }
    return i;
}
__device__ __forceinline__ int perm_inv(int i) {
#pragma unroll
    for (int j = 0; j < 12; j++) {
        int cb = 11 - j;
        int tb = (j == 11) ? 11 : (10 - j);
        i ^= ((i >> cb) & 1) << tb;
    }
    return i;
}

__global__ void __launch_bounds__(THREADS, 3) qsim_kernel(
    const float* __restrict__ x, const float* __restrict__ w,
    float* __restrict__ out)
{
    __shared__ float2 st[DIM];          // 32 KB state, swizzled
    __shared__ float gc[48], gs[48];    // cos/sin (0-11 = merged encode+layer0)
    __shared__ float gt[48];            // tan(theta/2) for deferred-scale gates
    __shared__ float sLA[16], sLB[16], sLC[16];  // product-state magnitude LUTs
    __shared__ float red[NQ];
    __shared__ float sS2;               // (prod of c over gates 12..47)^2

    const int b = blockIdx.x;
    const int t = threadIdx.x;

    // Angles. Slots 0-11: theta = x_q + w_{0,q} (RX fusion). 12-47: w rows 1-3.
    if (t < 48) {
        float th = w[t];
        if (t < NQ) th += x[b * NQ + t];
        float ss, cc;
        sincosf(0.5f * th, &ss, &cc);
        gc[t] = cc; gs[t] = ss;
        gt[t] = ss / cc;   // only slots 12-47 are consumed (weight gates, |t| small)
    }
    if (t < NQ) red[t] = 0.0f;
    __syncthreads();

    // Product-state magnitude LUTs over the three 4-bit nibbles (exact c,s).
    if (t < 48) {
        int grp = t >> 4;
        int h = t & 15;
        int qbase = grp * 4;
        float p = 1.0f;
#pragma unroll
        for (int q = 0; q < 4; q++)
            p *= ((h >> (3 - q)) & 1) ? gs[qbase + q] : gc[qbase + q];
        (grp == 0 ? sLA : grp == 1 ? sLB : sLC)[h] = p;
    }
    // Deferred global scale: S = prod c_g over gates 12..47 (block-uniform).
    if (t == 0) {
        float S = 1.0f;
#pragma unroll
        for (int g = 12; g < 48; g++) S *= gc[g];
        sS2 = S * S;
    }

    u64 X[8], Y[8];  // SoA packed state: pack k holds amps l=2k, 2k+1

    auto lidx = [&](int shift, int l) -> int {
        if (shift == 8) return (l << 8) | t;
        if (shift == 4) return ((t >> 4) << 8) | (l << 4) | (t & 15);
        return (t << 4) | l;
    };

    // pack-bit gate (l-mask 1) in tangent form on a freshly loaded pair, pack.
    auto gate_pack = [&](float2 a0, float2 a1, float t1, int k) {
        float nx0 = fmaf( t1, a1.y, a0.x);
        float ny0 = fmaf(-t1, a1.x, a0.y);
        float nx1 = fmaf( t1, a0.y, a1.x);
        float ny1 = fmaf(-t1, a0.x, a1.y);
        X[k] = pk2(nx0, nx1);
        Y[k] = pk2(ny0, ny1);
    };

    // Packed tangent-form RX on pack-space bit pm: 4 wide FMAs per pair.
    auto rxp = [&](int g, int pm) {
        float tg = gt[g];
        u64 t2 = pk2(tg, tg), m2 = pk2(-tg, -tg);
#pragma unroll
        for (int k = 0; k < 8; k++) {
            if (!(k & pm)) {
                int k1 = k | pm;
                u64 X0 = X[k], Y0 = Y[k], X1 = X[k1], Y1 = Y[k1];
                X[k]  = fma2(t2, Y1, X0);
                Y[k]  = fma2(m2, X1, Y0);
                X[k1] = fma2(t2, Y0, X1);
                Y[k1] = fma2(m2, X0, Y1);
            }
        }
    };
    auto packed3 = [&](int g) { rxp(g, 4); rxp(g + 1, 2); rxp(g + 2, 1); };

    auto load_pass = [&](int g, int shift) {
        float t1 = gt[g + 3];
#pragma unroll
        for (int k = 0; k < 8; k++)
            gate_pack(st[swz(lidx(shift, 2 * k))], st[swz(lidx(shift, 2 * k + 1))],
                      t1, k);
    };
    auto load_pass_perm = [&](int g) {
        float t1 = gt[g + 3];
        int pt = perm_fwd(t);
#pragma unroll
        for (int k = 0; k < 8; k++)
            gate_pack(st[swz(perm_fwd((2 * k) << 8) ^ pt)],
                      st[swz(perm_fwd((2 * k + 1) << 8) ^ pt)], t1, k);
    };
    auto store_pass = [&](int shift) {
#pragma unroll
        for (int k = 0; k < 8; k++) {
            float x0, x1, y0, y1;
            upk2(X[k], x0, x1);
            upk2(Y[k], y0, y1);
            st[swz(lidx(shift, 2 * k))]     = make_float2(x0, y0);
            st[swz(lidx(shift, 2 * k + 1))] = make_float2(x1, y1);
        }
    };

    // Analytic product-state amplitude: amp = mag(pi) * (-i)^popc(pi)
    auto prod_amp = [&](int pi) -> float2 {
        float mag = sLA[pi >> 8] * sLB[(pi >> 4) & 15] * sLC[pi & 15];
        int kc = __popc(pi) & 3;
        float sm = __int_as_float(__float_as_int(mag) ^ (((kc + 1) & 2) << 30));
        return (kc & 1) ? make_float2(0.0f, sm) : make_float2(sm, 0.0f);
    };

    __syncthreads();  // LUTs + sS2 ready

    // ---- Layer 1 (gates 12-23): group A analytic at perm-permuted indices ----
    {
        int pt = perm_fwd(t);
        float t1 = gt[15];
#pragma unroll
        for (int k = 0; k < 8; k++)
            gate_pack(prod_amp(perm_fwd((2 * k) << 8) ^ pt),
                      prod_amp(perm_fwd((2 * k + 1) << 8) ^ pt), t1, k);
        packed3(12);
        store_pass(8); __syncthreads();

        load_pass(16, 4); packed3(16); store_pass(4); __syncthreads();
        load_pass(20, 0); packed3(20); store_pass(0); __syncthreads();
    }

    // ---- Layers 2,3 (gates 24-35, 36-47) ----
#pragma unroll 1
    for (int layer = 2; layer <= 3; layer++) {
        int g = layer * 12;
        load_pass_perm(g);
        packed3(g);
        __syncthreads();     // scattered reads done before overwrite
        store_pass(8); __syncthreads();

        load_pass(g + 4, 4); packed3(g + 4); store_pass(4); __syncthreads();

        load_pass(g + 8, 0); packed3(g + 8);
        if (layer < 3) { store_pass(0); __syncthreads(); }
        // layer 3: stays in registers; final perm folded into readout
    }

    // ---- Readout: <Z_q> = S^2 * sum_i p_i * (1-2*bit_{11-q}(perm(i))) ----
    float acc[NQ];
#pragma unroll
    for (int q = 0; q < NQ; q++) acc[q] = 0.0f;
#pragma unroll
    for (int k = 0; k < 8; k++) {
        u64 P = fma2(X[k], X[k], mul2(Y[k], Y[k]));
        float p0, p1;
        upk2(P, p0, p1);
        const int pil0 = perm_inv(2 * k);      // compile-time constants
        const int pil1 = perm_inv(2 * k + 1);
#pragma unroll
        for (int q = 0; q < NQ; q++) {
            acc[q] += ((pil0 >> (11 - q)) & 1) ? -p0 : p0;
            acc[q] += ((pil1 >> (11 - q)) & 1) ? -p1 : p1;
        }
    }
    {
        int pit = perm_inv(t << 4);  // runtime per-thread sign factor
#pragma unroll
        for (int q = 0; q < NQ; q++)
            acc[q] = __int_as_float(__float_as_int(acc[q]) ^
                                    (((pit >> (11 - q)) & 1) << 31));
    }
#pragma unroll
    for (int off = 16; off > 0; off >>= 1) {
#pragma unroll
        for (int q = 0; q < NQ; q++)
            acc[q] += __shfl_xor_sync(0xffffffffu, acc[q], off);
    }
    if ((t & 31) == 0) {
#pragma unroll
        for (int q = 0; q < NQ; q++) atomicAdd(&red[q], acc[q]);
    }
    __syncthreads();
    if (t < NQ) out[b * NQ + t] = red[t] * sS2;  // apply deferred scale once
}

extern "C" void kernel_launch(void* const* d_in, const int* in_sizes, int n_in,
                              void* d_out, int out_size) {
    const float* x = (const float*)d_in[0];   // (64,128,12) float32
    const float* w = (const float*)d_in[1];   // (4,12) float32
    float* out = (float*)d_out;               // (64,128,12) float32
    int B = in_sizes[0] / NQ;                 // 8192
    qsim_kernel<<<B, THREADS>>>(x, w, out);
}